// round 16
// baseline (speedup 1.0000x reference)
#include <cuda_runtime.h>
#include <cstdint>

// x [4,2048,1024] fp32; Wq/Wk/Wv [1024,1024] fp32 -> out [4,2048,1024] fp32.

#define BATCH 4
#define SEQ   2048
#define DM    1024
#define MTOT  (BATCH * SEQ)   // 8192

#define BM 128
#define BN 128
#define NTH 256

// Scratch (no cudaMalloc allowed).
__device__ float g_X [MTOT * DM];            // rounded x, k-permuted
__device__ float g_Wt[3 * DM * DM];          // rounded W^T, k-permuted: [z][n][kperm]
__device__ float g_QK[2 * MTOT * DM];        // Q then K, rounded, d-permuted
__device__ float g_Vt[BATCH * DM * SEQ];     // V^T, s-permuted: [b][d][sperm]
__device__ float g_S [BATCH * SEQ * SEQ];    // scores / P, col(s)-permuted

// Within each 16-group, position p holds original offset (p%4)*4+p/4 (self-inverse).
__device__ __forceinline__ int porig(int i) {
    return (i & ~15) | ((i & 3) << 2) | ((i >> 2) & 3);
}

// ---------------------------------------------------------------------------
__device__ __forceinline__ uint32_t smem_u32(const void* p) {
    return (uint32_t)__cvta_generic_to_shared(p);
}
__device__ __forceinline__ void cp16(uint32_t s, const void* g) {
    asm volatile("cp.async.cg.shared.global [%0], [%1], 16;" :: "r"(s), "l"(g));
}
#define CP_COMMIT() asm volatile("cp.async.commit_group;")

__device__ __forceinline__ uint32_t f2tf(float f) {
    uint32_t u;
    asm("cvt.rna.tf32.f32 %0, %1;" : "=r"(u) : "f"(f));
    return u;
}
__device__ __forceinline__ float rnd_tf32(float f) { return __uint_as_float(f2tf(f)); }

__device__ __forceinline__ void mma8(float* c,
                                     float a0, float a1, float a2, float a3,
                                     float b0, float b1) {
    asm volatile(
        "mma.sync.aligned.m16n8k8.row.col.f32.tf32.tf32.f32 "
        "{%0,%1,%2,%3},{%4,%5,%6,%7},{%8,%9},{%0,%1,%2,%3};"
        : "+f"(c[0]), "+f"(c[1]), "+f"(c[2]), "+f"(c[3])
        : "r"(__float_as_uint(a0)), "r"(__float_as_uint(a1)),
          "r"(__float_as_uint(a2)), "r"(__float_as_uint(a3)),
          "r"(__float_as_uint(b0)), "r"(__float_as_uint(b1)));
}

// ---------------------------------------------------------------------------
// prep kernels
// ---------------------------------------------------------------------------
__global__ void prep_x_kernel(const float* __restrict__ x) {
    int i = blockIdx.x * blockDim.x + threadIdx.x;   // one 16-group per thread
    float4 in[4];
    #pragma unroll
    for (int j = 0; j < 4; j++) in[j] = ((const float4*)x)[i * 4 + j];
    const float* f = (const float*)in;
    #pragma unroll
    for (int u = 0; u < 4; u++) {
        float4 o = make_float4(rnd_tf32(f[u]), rnd_tf32(f[4 + u]),
                               rnd_tf32(f[8 + u]), rnd_tf32(f[12 + u]));
        ((float4*)g_X)[i * 4 + u] = o;
    }
}

// W[k][n] -> Wt[n][kperm], rounded.
__global__ void prep_w_kernel(const float* __restrict__ Wq,
                              const float* __restrict__ Wk,
                              const float* __restrict__ Wv) {
    __shared__ float tile[32][33];
    const float* W = (blockIdx.z == 0) ? Wq : (blockIdx.z == 1) ? Wk : Wv;
    float* Wt = g_Wt + (size_t)blockIdx.z * DM * DM;
    int nb = blockIdx.x * 32, kb = blockIdx.y * 32;
    int tx = threadIdx.x, ty = threadIdx.y;
    #pragma unroll
    for (int j = 0; j < 4; j++)
        tile[ty + 8 * j][tx] = W[(size_t)(kb + ty + 8 * j) * DM + nb + tx];
    __syncthreads();
    #pragma unroll
    for (int j = 0; j < 4; j++) {
        int n = ty + 8 * j;
        int ko = (tx & ~15) | ((tx & 3) << 2) | ((tx >> 2) & 3);
        Wt[(size_t)(nb + n) * DM + kb + tx] = rnd_tf32(tile[ko][n]);
    }
}

// ---------------------------------------------------------------------------
// tf32 mma GEMM: C[128,128] tile = A[m][kperm] @ B[n][kperm]^T.
// mode 0: QKV fused (bz 0/1 -> Q/K, round + perm cols;
//                    bz 2   -> Vt per batch [b][d][sperm], round).
// mode 2: scores (scale, perm cols, causal tile skip, heavy-tiles-first).
// mode 3: pv (linear, K truncated at diagonal, heavy-tiles-first).
// 3-stage cp.async ring, one __syncthreads per 16-k-group; prefetch issued
// AFTER the fragment LDS so MMAs start sooner.
// ---------------------------------------------------------------------------
#define BUF_FLOATS (128 * 16)
#define SMEM_DYN   (6 * BUF_FLOATS * 4)   // 49152 B (3 x A + 3 x B)

__global__ __launch_bounds__(NTH) void gemm_kernel(
    const float* __restrict__ Ag, const float* __restrict__ Bg,
    float* __restrict__ Cg, float* __restrict__ Cv,
    int ldA, int ldB, int ldC,
    long long strideAz, long long strideBz, long long strideCz,
    int kGroupsFull, float scale, int mode)
{
    // Heavy-tiles-first for causal kernels.
    const int by = (mode >= 2) ? (gridDim.y - 1 - blockIdx.y) : blockIdx.y;
    const int bx = blockIdx.x, bz = blockIdx.z;
    if (mode == 2 && bx > by) return;
    const int kG = (mode == 3) ? (by + 1) * 8 : kGroupsFull;   // 16-float groups

    const float* A = Ag + (size_t)bz * strideAz + (size_t)by * BM * ldA;
    const float* B = Bg + (size_t)bz * strideBz + (size_t)bx * BN * ldB;

    extern __shared__ float dsm[];
    float* As = dsm;                       // [3][128][16]
    float* Bs = dsm + 3 * BUF_FLOATS;      // [3][128][16]

    const int t    = threadIdx.x;
    const int lane = t & 31;
    const int warp = t >> 5;
    const int gid  = lane >> 2;
    const int tig  = lane & 3;
    const int wm   = warp & 1;             // 2 warp-rows of 64
    const int wn   = warp >> 1;            // 4 warp-cols of 32

    float acc[4][4][4] = {};

    auto load_group = [&](int g, int buf) {
        float* Ad = As + buf * BUF_FLOATS;
        float* Bd = Bs + buf * BUF_FLOATS;
        #pragma unroll
        for (int j = 0; j < 2; j++) {
            int idx = t + j * NTH;                // 0..511
            int r = idx >> 2, q = idx & 3;
            cp16(smem_u32(Ad + r * 16 + q * 4), A + (size_t)r * ldA + g * 16 + q * 4);
        }
        #pragma unroll
        for (int j = 0; j < 2; j++) {
            int idx = t + j * NTH;
            int r = idx >> 2, q = idx & 3;
            cp16(smem_u32(Bd + r * 16 + q * 4), B + (size_t)r * ldB + g * 16 + q * 4);
        }
        CP_COMMIT();
    };

    load_group(0, 0);
    load_group(1, 1);

    const int aRow0 = wm * 64 + gid;
    const int bCol0 = wn * 32 + gid;

    int buf = 0;
    for (int g = 0; g < kG; g++) {
        if (g + 1 < kG) asm volatile("cp.async.wait_group 1;");
        else            asm volatile("cp.async.wait_group 0;");
        __syncthreads();

        const float* Ab = As + buf * BUF_FLOATS;
        const float* Bb = Bs + buf * BUF_FLOATS;
        // Fragment LDS first so MMAs can start as soon as data lands...
        float4 fa[4], fa2[4];
        #pragma unroll
        for (int mt = 0; mt < 4; mt++) {
            int r = aRow0 + mt * 16;
            fa[mt]  = *(const float4*)(Ab + r * 16 + tig * 4);
            fa2[mt] = *(const float4*)(Ab + (r + 8) * 16 + tig * 4);
        }
        // ...then issue the prefetch for g+2 into the buffer freed by
        // iteration g-1 (safe after the sync above); it overlaps LDS latency.
        if (g + 2 < kG) {
            int nb = buf - 1; if (nb < 0) nb = 2;
            load_group(g + 2, nb);
        }
        #pragma unroll
        for (int nt = 0; nt < 4; nt++) {
            float4 fb = *(const float4*)(Bb + (bCol0 + nt * 8) * 16 + tig * 4);
            #pragma unroll
            for (int mt = 0; mt < 4; mt++) {
                mma8(acc[mt][nt], fa[mt].x, fa2[mt].x, fa[mt].y, fa2[mt].y, fb.x, fb.y);
                mma8(acc[mt][nt], fa[mt].z, fa2[mt].z, fa[mt].w, fa2[mt].w, fb.z, fb.w);
            }
        }
        buf++; if (buf == 3) buf = 0;
    }

    // ------------------------------------------------------------------ epilogue
    const bool vtrans  = (mode == 0) && (bz == 2);
    const bool doRound = (mode == 0);
    const bool permOut = ((mode == 0) && (bz < 2)) || (mode == 2);
    float* C = vtrans ? nullptr
                      : Cg + (size_t)bz * strideCz + (size_t)by * BM * ldC + bx * BN;

    float (*stage)[69] = (float(*)[69])dsm;      // 128 x 69 = 35328 B < 49152

    #pragma unroll
    for (int h = 0; h < 2; h++) {
        __syncthreads();
        if ((wn >> 1) == h) {
            #pragma unroll
            for (int mt = 0; mt < 4; mt++) {
                int r1 = wm * 64 + mt * 16 + gid;
                #pragma unroll
                for (int nt = 0; nt < 4; nt++) {
                    int cl = (wn & 1) * 32 + nt * 8 + tig * 2;
                    float v0 = acc[mt][nt][0] * scale, v1 = acc[mt][nt][1] * scale;
                    float v2 = acc[mt][nt][2] * scale, v3 = acc[mt][nt][3] * scale;
                    if (doRound) {
                        v0 = rnd_tf32(v0); v1 = rnd_tf32(v1);
                        v2 = rnd_tf32(v2); v3 = rnd_tf32(v3);
                    }
                    stage[r1][cl] = v0;     stage[r1][cl + 1] = v1;
                    stage[r1 + 8][cl] = v2; stage[r1 + 8][cl + 1] = v3;
                }
            }
        }
        __syncthreads();
        if (vtrans) {
            // Vt[b][d][sperm]: batch = by>>4, local s base = (by&15)*128.
            const int c    = t & 63;
            const int sub  = t >> 6;           // 0..3 -> 32-row span
            const int bb   = by >> 4;
            const int sloc = (by & 15) * BM;
            float* dst = Cv + (size_t)bb * DM * SEQ
                            + (size_t)(bx * BN + h * 64 + c) * SEQ
                            + sloc + sub * 32;
            #pragma unroll
            for (int u = 0; u < 8; u++) {
                int j = sub * 32 + u * 4;
                int g0 = j & ~15, a = (j >> 2) & 3;
                float4 v = make_float4(stage[g0 + a][c],      stage[g0 + 4 + a][c],
                                       stage[g0 + 8 + a][c],  stage[g0 + 12 + a][c]);
                *(float4*)(dst + u * 4) = v;
            }
        } else {
            const int rr  = t & 127;
            const int sub = t >> 7;            // 0..1 -> 32-col subhalf
            float* dst = C + (size_t)rr * ldC + h * 64 + sub * 32;
            const float* src = stage[rr] + sub * 32;
            if (permOut) {
                #pragma unroll
                for (int gi = 0; gi < 2; gi++) {
                    #pragma unroll
                    for (int u = 0; u < 4; u++) {
                        float4 v = make_float4(src[gi * 16 + u],     src[gi * 16 + u + 4],
                                               src[gi * 16 + u + 8], src[gi * 16 + u + 12]);
                        *(float4*)(dst + gi * 16 + u * 4) = v;
                    }
                }
            } else {
                #pragma unroll
                for (int u = 0; u < 8; u++) {
                    float4 v = make_float4(src[u * 4], src[u * 4 + 1],
                                           src[u * 4 + 2], src[u * 4 + 3]);
                    *(float4*)(dst + u * 4) = v;
                }
            }
        }
    }
}

// ---------------------------------------------------------------------------
// Causal softmax over permuted rows (float4-vectorized, heavy rows first);
// rounds P to tf32; fills only the extent pv reads (next 128 boundary).
// ---------------------------------------------------------------------------
__global__ __launch_bounds__(NTH) void softmax_kernel()
{
    __shared__ float buf[SEQ];
    __shared__ float red[8];

    const int row = gridDim.x - 1 - blockIdx.x;   // heavy (long) rows first
    const int b = row >> 11;
    const int q = row & (SEQ - 1);
    float* S = g_S + ((size_t)b * SEQ + q) * SEQ;
    const int L = q + 1;
    const int Lcap  = (L + 15) & ~15;            // boundary 16-group
    const int Lfill = ((q >> 7) + 1) << 7;       // pv read extent
    const int t = threadIdx.x;

    const float NEG = -3.402823e38f;
    float mx = NEG;
    for (int i = 4 * t; i < Lcap; i += 4 * NTH) {
        float4 v = *(const float4*)&S[i];
        *(float4*)&buf[i] = v;
        int g0 = i & ~15, u = (i >> 2) & 3;
        int o = g0 + u;
        if (o < L)      mx = fmaxf(mx, v.x);
        if (o + 4 < L)  mx = fmaxf(mx, v.y);
        if (o + 8 < L)  mx = fmaxf(mx, v.z);
        if (o + 12 < L) mx = fmaxf(mx, v.w);
    }
    #pragma unroll
    for (int o = 16; o; o >>= 1) mx = fmaxf(mx, __shfl_xor_sync(0xFFFFFFFFu, mx, o));
    if ((t & 31) == 0) red[t >> 5] = mx;
    __syncthreads();
    float m = red[0];
    #pragma unroll
    for (int i = 1; i < 8; i++) m = fmaxf(m, red[i]);
    __syncthreads();

    float sum = 0.0f;
    for (int i = 4 * t; i < Lcap; i += 4 * NTH) {
        float4 v = *(const float4*)&buf[i];
        int g0 = i & ~15, u = (i >> 2) & 3;
        int o = g0 + u;
        float e0 = (o < L)      ? __expf(v.x - m) : 0.0f;
        float e1 = (o + 4 < L)  ? __expf(v.y - m) : 0.0f;
        float e2 = (o + 8 < L)  ? __expf(v.z - m) : 0.0f;
        float e3 = (o + 12 < L) ? __expf(v.w - m) : 0.0f;
        *(float4*)&buf[i] = make_float4(e0, e1, e2, e3);
        sum += (e0 + e1) + (e2 + e3);
    }
    #pragma unroll
    for (int o = 16; o; o >>= 1) sum += __shfl_xor_sync(0xFFFFFFFFu, sum, o);
    if ((t & 31) == 0) red[t >> 5] = sum;
    __syncthreads();
    float s = 0.0f;
    #pragma unroll
    for (int i = 0; i < 8; i++) s += red[i];
    const float inv = 1.0f / s;

    for (int i = 4 * t; i < Lfill; i += 4 * NTH) {
        float4 o4 = make_float4(0.0f, 0.0f, 0.0f, 0.0f);
        if (i < Lcap) {
            float4 v = *(const float4*)&buf[i];
            o4.x = rnd_tf32(v.x * inv);
            o4.y = rnd_tf32(v.y * inv);
            o4.z = rnd_tf32(v.z * inv);
            o4.w = rnd_tf32(v.w * inv);
        }
        *(float4*)&S[i] = o4;
    }
}

// ---------------------------------------------------------------------------
extern "C" void kernel_launch(void* const* d_in, const int* in_sizes, int n_in,
                              void* d_out, int out_size)
{
    const float* x  = (const float*)d_in[0];
    const float* Wq = (const float*)d_in[1];
    const float* Wk = (const float*)d_in[2];
    const float* Wv = (const float*)d_in[3];
    float* out = (float*)d_out;

    cudaFuncSetAttribute(gemm_kernel, cudaFuncAttributeMaxDynamicSharedMemorySize, SMEM_DYN);

    float *pX, *pWt, *pQK, *pVt, *pS;
    cudaGetSymbolAddress((void**)&pX,  g_X);
    cudaGetSymbolAddress((void**)&pWt, g_Wt);
    cudaGetSymbolAddress((void**)&pQK, g_QK);
    cudaGetSymbolAddress((void**)&pVt, g_Vt);
    cudaGetSymbolAddress((void**)&pS,  g_S);

    prep_x_kernel<<<2048, 256>>>(x);
    prep_w_kernel<<<dim3(32, 32, 3), dim3(32, 8)>>>(Wq, Wk, Wv);

    // QKV fused: z=0 -> Q, z=1 -> K (row-major, perm), z=2 -> Vt (per-batch transpose).
    gemm_kernel<<<dim3(8, 64, 3), NTH, SMEM_DYN>>>(
        pX, pWt, pQK, pVt, DM, DM, DM,
        0, (long long)DM * DM, (long long)MTOT * DM,
        64, 1.0f, 0);

    // Scores: S = (Q @ K^T) * scale, lower tiles only, permuted cols.
    gemm_kernel<<<dim3(16, 16, BATCH), NTH, SMEM_DYN>>>(
        pQK, pQK + (size_t)MTOT * DM, pS, nullptr, DM, DM, SEQ,
        (long long)SEQ * DM, (long long)SEQ * DM, (long long)SEQ * SEQ,
        64, 0.03125f, 2);

    softmax_kernel<<<MTOT, NTH>>>();

    // PV: O = P @ Vt^T, K truncated at diagonal, linear output.
    gemm_kernel<<<dim3(8, 16, BATCH), NTH, SMEM_DYN>>>(
        pS, pVt, out, nullptr, SEQ, SEQ, DM,
        (long long)SEQ * SEQ, (long long)DM * SEQ, (long long)SEQ * DM,
        128, 1.0f, 3);
}

// round 17
// speedup vs baseline: 1.2843x; 1.2843x over previous
#include <cuda_runtime.h>
#include <cstdint>

// x [4,2048,1024] fp32; Wq/Wk/Wv [1024,1024] fp32 -> out [4,2048,1024] fp32.

#define BATCH 4
#define SEQ   2048
#define DM    1024
#define MTOT  (BATCH * SEQ)   // 8192

#define BM 128
#define BN 128
#define NTH 256

// Scratch (no cudaMalloc allowed).
__device__ float g_X [MTOT * DM];            // rounded x, k-permuted
__device__ float g_Wt[3 * DM * DM];          // rounded W^T, k-permuted: [z][n][kperm]
__device__ float g_QK[2 * MTOT * DM];        // Q then K, rounded, d-permuted
__device__ float g_Vt[BATCH * DM * SEQ];     // V^T, s-permuted: [b][d][sperm]
__device__ float g_S [BATCH * SEQ * SEQ];    // scores / P, col(s)-permuted

// Within each 16-group, position p holds original offset (p%4)*4+p/4 (self-inverse).
__device__ __forceinline__ int porig(int i) {
    return (i & ~15) | ((i & 3) << 2) | ((i >> 2) & 3);
}

// ---------------------------------------------------------------------------
__device__ __forceinline__ uint32_t smem_u32(const void* p) {
    return (uint32_t)__cvta_generic_to_shared(p);
}
__device__ __forceinline__ void cp16(uint32_t s, const void* g) {
    asm volatile("cp.async.cg.shared.global [%0], [%1], 16;" :: "r"(s), "l"(g));
}
#define CP_COMMIT() asm volatile("cp.async.commit_group;")

__device__ __forceinline__ uint32_t f2tf(float f) {
    uint32_t u;
    asm("cvt.rna.tf32.f32 %0, %1;" : "=r"(u) : "f"(f));
    return u;
}
__device__ __forceinline__ float rnd_tf32(float f) { return __uint_as_float(f2tf(f)); }

__device__ __forceinline__ void mma8(float* c,
                                     float a0, float a1, float a2, float a3,
                                     float b0, float b1) {
    asm volatile(
        "mma.sync.aligned.m16n8k8.row.col.f32.tf32.tf32.f32 "
        "{%0,%1,%2,%3},{%4,%5,%6,%7},{%8,%9},{%0,%1,%2,%3};"
        : "+f"(c[0]), "+f"(c[1]), "+f"(c[2]), "+f"(c[3])
        : "r"(__float_as_uint(a0)), "r"(__float_as_uint(a1)),
          "r"(__float_as_uint(a2)), "r"(__float_as_uint(a3)),
          "r"(__float_as_uint(b0)), "r"(__float_as_uint(b1)));
}

// ---------------------------------------------------------------------------
// prep kernels
// ---------------------------------------------------------------------------
__global__ void prep_x_kernel(const float* __restrict__ x) {
    int i = blockIdx.x * blockDim.x + threadIdx.x;   // one 16-group per thread
    float4 in[4];
    #pragma unroll
    for (int j = 0; j < 4; j++) in[j] = ((const float4*)x)[i * 4 + j];
    const float* f = (const float*)in;
    #pragma unroll
    for (int u = 0; u < 4; u++) {
        float4 o = make_float4(rnd_tf32(f[u]), rnd_tf32(f[4 + u]),
                               rnd_tf32(f[8 + u]), rnd_tf32(f[12 + u]));
        ((float4*)g_X)[i * 4 + u] = o;
    }
}

// W[k][n] -> Wt[n][kperm], rounded.
__global__ void prep_w_kernel(const float* __restrict__ Wq,
                              const float* __restrict__ Wk,
                              const float* __restrict__ Wv) {
    __shared__ float tile[32][33];
    const float* W = (blockIdx.z == 0) ? Wq : (blockIdx.z == 1) ? Wk : Wv;
    float* Wt = g_Wt + (size_t)blockIdx.z * DM * DM;
    int nb = blockIdx.x * 32, kb = blockIdx.y * 32;
    int tx = threadIdx.x, ty = threadIdx.y;
    #pragma unroll
    for (int j = 0; j < 4; j++)
        tile[ty + 8 * j][tx] = W[(size_t)(kb + ty + 8 * j) * DM + nb + tx];
    __syncthreads();
    #pragma unroll
    for (int j = 0; j < 4; j++) {
        int n = ty + 8 * j;
        int ko = (tx & ~15) | ((tx & 3) << 2) | ((tx >> 2) & 3);
        Wt[(size_t)(nb + n) * DM + kb + tx] = rnd_tf32(tile[ko][n]);
    }
}

// ---------------------------------------------------------------------------
// tf32 mma GEMM: C[128,128] tile = A[m][kperm] @ B[n][kperm]^T.
// mode 0: QKV fused (bz 0/1 -> Q/K, round + perm cols;
//                    bz 2   -> Vt per batch [b][d][sperm], round).
// mode 2: scores (scale, perm cols, causal tile skip, heavy-tiles-first).
// mode 3: pv (linear, K truncated at diagonal, heavy-tiles-first).
// 3-stage cp.async ring, one __syncthreads per 16-k-group.
// (FROZEN: byte-identical to the 630us champion — do not perturb.)
// ---------------------------------------------------------------------------
#define BUF_FLOATS (128 * 16)
#define SMEM_DYN   (6 * BUF_FLOATS * 4)   // 49152 B (3 x A + 3 x B)

__global__ __launch_bounds__(NTH) void gemm_kernel(
    const float* __restrict__ Ag, const float* __restrict__ Bg,
    float* __restrict__ Cg, float* __restrict__ Cv,
    int ldA, int ldB, int ldC,
    long long strideAz, long long strideBz, long long strideCz,
    int kGroupsFull, float scale, int mode)
{
    // Heavy-tiles-first for causal kernels.
    const int by = (mode >= 2) ? (gridDim.y - 1 - blockIdx.y) : blockIdx.y;
    const int bx = blockIdx.x, bz = blockIdx.z;
    if (mode == 2 && bx > by) return;
    const int kG = (mode == 3) ? (by + 1) * 8 : kGroupsFull;   // 16-float groups

    const float* A = Ag + (size_t)bz * strideAz + (size_t)by * BM * ldA;
    const float* B = Bg + (size_t)bz * strideBz + (size_t)bx * BN * ldB;

    extern __shared__ float dsm[];
    float* As = dsm;                       // [3][128][16]
    float* Bs = dsm + 3 * BUF_FLOATS;      // [3][128][16]

    const int t    = threadIdx.x;
    const int lane = t & 31;
    const int warp = t >> 5;
    const int gid  = lane >> 2;
    const int tig  = lane & 3;
    const int wm   = warp & 1;             // 2 warp-rows of 64
    const int wn   = warp >> 1;            // 4 warp-cols of 32

    float acc[4][4][4] = {};

    auto load_group = [&](int g, int buf) {
        float* Ad = As + buf * BUF_FLOATS;
        float* Bd = Bs + buf * BUF_FLOATS;
        #pragma unroll
        for (int j = 0; j < 2; j++) {
            int idx = t + j * NTH;                // 0..511
            int r = idx >> 2, q = idx & 3;
            cp16(smem_u32(Ad + r * 16 + q * 4), A + (size_t)r * ldA + g * 16 + q * 4);
        }
        #pragma unroll
        for (int j = 0; j < 2; j++) {
            int idx = t + j * NTH;
            int r = idx >> 2, q = idx & 3;
            cp16(smem_u32(Bd + r * 16 + q * 4), B + (size_t)r * ldB + g * 16 + q * 4);
        }
        CP_COMMIT();
    };

    load_group(0, 0);
    load_group(1, 1);

    const int aRow0 = wm * 64 + gid;
    const int bCol0 = wn * 32 + gid;

    int buf = 0;
    for (int g = 0; g < kG; g++) {
        if (g + 1 < kG) asm volatile("cp.async.wait_group 1;");
        else            asm volatile("cp.async.wait_group 0;");
        __syncthreads();
        // Prefetch g+2 into the buffer freed by iteration g-1 (safe after sync).
        if (g + 2 < kG) {
            int nb = buf - 1; if (nb < 0) nb = 2;
            load_group(g + 2, nb);
        }

        const float* Ab = As + buf * BUF_FLOATS;
        const float* Bb = Bs + buf * BUF_FLOATS;
        float4 fa[4], fa2[4];
        #pragma unroll
        for (int mt = 0; mt < 4; mt++) {
            int r = aRow0 + mt * 16;
            fa[mt]  = *(const float4*)(Ab + r * 16 + tig * 4);
            fa2[mt] = *(const float4*)(Ab + (r + 8) * 16 + tig * 4);
        }
        #pragma unroll
        for (int nt = 0; nt < 4; nt++) {
            float4 fb = *(const float4*)(Bb + (bCol0 + nt * 8) * 16 + tig * 4);
            #pragma unroll
            for (int mt = 0; mt < 4; mt++) {
                mma8(acc[mt][nt], fa[mt].x, fa2[mt].x, fa[mt].y, fa2[mt].y, fb.x, fb.y);
                mma8(acc[mt][nt], fa[mt].z, fa2[mt].z, fa[mt].w, fa2[mt].w, fb.z, fb.w);
            }
        }
        buf++; if (buf == 3) buf = 0;
    }

    // ------------------------------------------------------------------ epilogue
    const bool vtrans  = (mode == 0) && (bz == 2);
    const bool doRound = (mode == 0);
    const bool permOut = ((mode == 0) && (bz < 2)) || (mode == 2);
    float* C = vtrans ? nullptr
                      : Cg + (size_t)bz * strideCz + (size_t)by * BM * ldC + bx * BN;

    float (*stage)[69] = (float(*)[69])dsm;      // 128 x 69 = 35328 B < 49152

    #pragma unroll
    for (int h = 0; h < 2; h++) {
        __syncthreads();
        if ((wn >> 1) == h) {
            #pragma unroll
            for (int mt = 0; mt < 4; mt++) {
                int r1 = wm * 64 + mt * 16 + gid;
                #pragma unroll
                for (int nt = 0; nt < 4; nt++) {
                    int cl = (wn & 1) * 32 + nt * 8 + tig * 2;
                    float v0 = acc[mt][nt][0] * scale, v1 = acc[mt][nt][1] * scale;
                    float v2 = acc[mt][nt][2] * scale, v3 = acc[mt][nt][3] * scale;
                    if (doRound) {
                        v0 = rnd_tf32(v0); v1 = rnd_tf32(v1);
                        v2 = rnd_tf32(v2); v3 = rnd_tf32(v3);
                    }
                    stage[r1][cl] = v0;     stage[r1][cl + 1] = v1;
                    stage[r1 + 8][cl] = v2; stage[r1 + 8][cl + 1] = v3;
                }
            }
        }
        __syncthreads();
        if (vtrans) {
            // Vt[b][d][sperm]: batch = by>>4, local s base = (by&15)*128.
            const int c    = t & 63;
            const int sub  = t >> 6;           // 0..3 -> 32-row span
            const int bb   = by >> 4;
            const int sloc = (by & 15) * BM;
            float* dst = Cv + (size_t)bb * DM * SEQ
                            + (size_t)(bx * BN + h * 64 + c) * SEQ
                            + sloc + sub * 32;
            #pragma unroll
            for (int u = 0; u < 8; u++) {
                int j = sub * 32 + u * 4;
                int g0 = j & ~15, a = (j >> 2) & 3;
                float4 v = make_float4(stage[g0 + a][c],      stage[g0 + 4 + a][c],
                                       stage[g0 + 8 + a][c],  stage[g0 + 12 + a][c]);
                *(float4*)(dst + u * 4) = v;
            }
        } else {
            const int rr  = t & 127;
            const int sub = t >> 7;            // 0..1 -> 32-col subhalf
            float* dst = C + (size_t)rr * ldC + h * 64 + sub * 32;
            const float* src = stage[rr] + sub * 32;
            if (permOut) {
                #pragma unroll
                for (int gi = 0; gi < 2; gi++) {
                    #pragma unroll
                    for (int u = 0; u < 4; u++) {
                        float4 v = make_float4(src[gi * 16 + u],     src[gi * 16 + u + 4],
                                               src[gi * 16 + u + 8], src[gi * 16 + u + 12]);
                        *(float4*)(dst + gi * 16 + u * 4) = v;
                    }
                }
            } else {
                #pragma unroll
                for (int u = 0; u < 8; u++) {
                    float4 v = make_float4(src[u * 4], src[u * 4 + 1],
                                           src[u * 4 + 2], src[u * 4 + 3]);
                    *(float4*)(dst + u * 4) = v;
                }
            }
        }
    }
}

// ---------------------------------------------------------------------------
// Causal softmax over permuted rows (float4-vectorized, heavy rows first);
// rounds P to tf32; fills only the extent pv reads (next 128 boundary).
// ---------------------------------------------------------------------------
__global__ __launch_bounds__(NTH) void softmax_kernel()
{
    __shared__ float buf[SEQ];
    __shared__ float red[8];

    const int row = gridDim.x - 1 - blockIdx.x;   // heavy (long) rows first
    const int b = row >> 11;
    const int q = row & (SEQ - 1);
    float* S = g_S + ((size_t)b * SEQ + q) * SEQ;
    const int L = q + 1;
    const int Lcap  = (L + 15) & ~15;            // boundary 16-group
    const int Lfill = ((q >> 7) + 1) << 7;       // pv read extent
    const int t = threadIdx.x;

    const float NEG = -3.402823e38f;
    float mx = NEG;
    for (int i = 4 * t; i < Lcap; i += 4 * NTH) {
        float4 v = *(const float4*)&S[i];
        *(float4*)&buf[i] = v;
        int g0 = i & ~15, u = (i >> 2) & 3;
        int o = g0 + u;
        if (o < L)      mx = fmaxf(mx, v.x);
        if (o + 4 < L)  mx = fmaxf(mx, v.y);
        if (o + 8 < L)  mx = fmaxf(mx, v.z);
        if (o + 12 < L) mx = fmaxf(mx, v.w);
    }
    #pragma unroll
    for (int o = 16; o; o >>= 1) mx = fmaxf(mx, __shfl_xor_sync(0xFFFFFFFFu, mx, o));
    if ((t & 31) == 0) red[t >> 5] = mx;
    __syncthreads();
    float m = red[0];
    #pragma unroll
    for (int i = 1; i < 8; i++) m = fmaxf(m, red[i]);
    __syncthreads();

    float sum = 0.0f;
    for (int i = 4 * t; i < Lcap; i += 4 * NTH) {
        float4 v = *(const float4*)&buf[i];
        int g0 = i & ~15, u = (i >> 2) & 3;
        int o = g0 + u;
        float e0 = (o < L)      ? __expf(v.x - m) : 0.0f;
        float e1 = (o + 4 < L)  ? __expf(v.y - m) : 0.0f;
        float e2 = (o + 8 < L)  ? __expf(v.z - m) : 0.0f;
        float e3 = (o + 12 < L) ? __expf(v.w - m) : 0.0f;
        *(float4*)&buf[i] = make_float4(e0, e1, e2, e3);
        sum += (e0 + e1) + (e2 + e3);
    }
    #pragma unroll
    for (int o = 16; o; o >>= 1) sum += __shfl_xor_sync(0xFFFFFFFFu, sum, o);
    if ((t & 31) == 0) red[t >> 5] = sum;
    __syncthreads();
    float s = 0.0f;
    #pragma unroll
    for (int i = 0; i < 8; i++) s += red[i];
    const float inv = 1.0f / s;

    for (int i = 4 * t; i < Lfill; i += 4 * NTH) {
        float4 o4 = make_float4(0.0f, 0.0f, 0.0f, 0.0f);
        if (i < Lcap) {
            float4 v = *(const float4*)&buf[i];
            o4.x = rnd_tf32(v.x * inv);
            o4.y = rnd_tf32(v.y * inv);
            o4.z = rnd_tf32(v.z * inv);
            o4.w = rnd_tf32(v.w * inv);
        }
        *(float4*)&S[i] = o4;
    }
}

// ---------------------------------------------------------------------------
extern "C" void kernel_launch(void* const* d_in, const int* in_sizes, int n_in,
                              void* d_out, int out_size)
{
    const float* x  = (const float*)d_in[0];
    const float* Wq = (const float*)d_in[1];
    const float* Wk = (const float*)d_in[2];
    const float* Wv = (const float*)d_in[3];
    float* out = (float*)d_out;

    cudaFuncSetAttribute(gemm_kernel, cudaFuncAttributeMaxDynamicSharedMemorySize, SMEM_DYN);

    float *pX, *pWt, *pQK, *pVt, *pS;
    cudaGetSymbolAddress((void**)&pX,  g_X);
    cudaGetSymbolAddress((void**)&pWt, g_Wt);
    cudaGetSymbolAddress((void**)&pQK, g_QK);
    cudaGetSymbolAddress((void**)&pVt, g_Vt);
    cudaGetSymbolAddress((void**)&pS,  g_S);

    prep_x_kernel<<<2048, 256>>>(x);
    prep_w_kernel<<<dim3(32, 32, 3), dim3(32, 8)>>>(Wq, Wk, Wv);

    // QKV fused: z=0 -> Q, z=1 -> K (row-major, perm), z=2 -> Vt (per-batch transpose).
    gemm_kernel<<<dim3(8, 64, 3), NTH, SMEM_DYN>>>(
        pX, pWt, pQK, pVt, DM, DM, DM,
        0, (long long)DM * DM, (long long)MTOT * DM,
        64, 1.0f, 0);

    // Scores: S = (Q @ K^T) * scale, lower tiles only, permuted cols.
    gemm_kernel<<<dim3(16, 16, BATCH), NTH, SMEM_DYN>>>(
        pQK, pQK + (size_t)MTOT * DM, pS, nullptr, DM, DM, SEQ,
        (long long)SEQ * DM, (long long)SEQ * DM, (long long)SEQ * SEQ,
        64, 0.03125f, 2);

    softmax_kernel<<<MTOT, NTH>>>();

    // PV: O = P @ Vt^T, K truncated at diagonal, linear output.
    gemm_kernel<<<dim3(8, 16, BATCH), NTH, SMEM_DYN>>>(
        pS, pVt, out, nullptr, SEQ, SEQ, DM,
        (long long)SEQ * SEQ, (long long)DM * SEQ, (long long)SEQ * DM,
        128, 1.0f, 3);
}